// round 4
// baseline (speedup 1.0000x reference)
#include <cuda_runtime.h>
#include <stdint.h>

// Problem constants
#define N_SRC0 200000
#define N_DST0 50000
#define N_DST1 10000
#define NE0    800000
#define NE1    160000
#define DIM    256
#define NBASE  4
#define BD     64
#define NPAIR  5000

// ---------------------------------------------------------------------------
// Scratch (__device__ globals; kernels reference them directly)
// ---------------------------------------------------------------------------
__device__ float g_agg0[(size_t)N_DST0 * DIM];
__device__ float g_agg1[(size_t)N_DST1 * DIM];
__device__ float g_h0  [(size_t)N_DST0 * DIM];
__device__ float g_h1  [(size_t)N_DST1 * DIM];

__device__ int g_cnt0[N_DST0];
__device__ int g_cnt1[N_DST1];
__device__ int g_rowptr0[N_DST0 + 1];
__device__ int g_rowptr1[N_DST1 + 1];
__device__ int g_cur0[N_DST0];
__device__ int g_cur1[N_DST1];
__device__ int g_esrc0[NE0];
__device__ int g_esrc1[NE1];

// ---------------------------------------------------------------------------
// Zero the per-dst edge counters
// ---------------------------------------------------------------------------
__global__ void zero_cnt_kernel() {
    int stride = gridDim.x * blockDim.x;
    int i0 = blockIdx.x * blockDim.x + threadIdx.x;
    for (int i = i0; i < N_DST0; i += stride) g_cnt0[i] = 0;
    for (int i = i0; i < N_DST1; i += stride) g_cnt1[i] = 0;
}

// ---------------------------------------------------------------------------
// CSR build: count, scan, fill
// ---------------------------------------------------------------------------
template <int WHICH>
__global__ void count_kernel(const int* __restrict__ dst, int ne) {
    int* cnt = WHICH ? g_cnt1 : g_cnt0;
    int e = blockIdx.x * blockDim.x + threadIdx.x;
    if (e < ne) atomicAdd(&cnt[dst[e]], 1);
}

// Single-block exclusive scan (1024 threads, warp-shuffle based).
template <int WHICH>
__global__ __launch_bounds__(1024) void scan_kernel() {
    const int* cnt = WHICH ? g_cnt1 : g_cnt0;
    int* rowptr    = WHICH ? g_rowptr1 : g_rowptr0;
    int* cur       = WHICH ? g_cur1 : g_cur0;
    const int n    = WHICH ? N_DST1 : N_DST0;

    __shared__ int wsum[32];
    __shared__ int carry_s;
    int tid = threadIdx.x, lane = tid & 31, wid = tid >> 5;
    if (tid == 0) carry_s = 0;
    __syncthreads();

    for (int base = 0; base < n; base += 1024) {
        int i = base + tid;
        int v = (i < n) ? cnt[i] : 0;
        // intra-warp inclusive scan
        int incl = v;
        #pragma unroll
        for (int o = 1; o < 32; o <<= 1) {
            int t = __shfl_up_sync(0xFFFFFFFFu, incl, o);
            if (lane >= o) incl += t;
        }
        if (lane == 31) wsum[wid] = incl;
        __syncthreads();
        if (wid == 0) {
            int w = wsum[lane];
            int wi = w;
            #pragma unroll
            for (int o = 1; o < 32; o <<= 1) {
                int t = __shfl_up_sync(0xFFFFFFFFu, wi, o);
                if (lane >= o) wi += t;
            }
            wsum[lane] = wi - w;   // exclusive warp offsets
        }
        __syncthreads();
        int excl = incl - v + wsum[wid] + carry_s;
        if (i < n) { rowptr[i] = excl; cur[i] = excl; }
        __syncthreads();           // everyone read carry_s before update
        if (tid == 1023) carry_s = excl + v;   // absolute running total
        __syncthreads();
    }
    if (tid == 0) rowptr[n] = carry_s;
}

template <int WHICH>
__global__ void fill_kernel(const int* __restrict__ src,
                            const int* __restrict__ dst, int ne) {
    int* cur  = WHICH ? g_cur1 : g_cur0;
    int* esrc = WHICH ? g_esrc1 : g_esrc0;
    int e = blockIdx.x * blockDim.x + threadIdx.x;
    if (e < ne) {
        int p = atomicAdd(&cur[dst[e]], 1);
        esrc[p] = src[e];
    }
}

// ---------------------------------------------------------------------------
// Pull-mode aggregation: agg[d, :] = sum over edges of feat[src, :]
// 128 threads per block = 2 dst rows, 64 threads (float4 each) per row.
// ---------------------------------------------------------------------------
template <int WHICH>
__global__ __launch_bounds__(128) void gather_kernel(const float* __restrict__ featp) {
    const float* feat  = WHICH ? g_h0 : featp;
    float* agg         = WHICH ? g_agg1 : g_agg0;
    const int* rowptr  = WHICH ? g_rowptr1 : g_rowptr0;
    const int* esrc    = WHICH ? g_esrc1 : g_esrc0;
    const int ndst     = WHICH ? N_DST1 : N_DST0;

    int d = blockIdx.x * 2 + (threadIdx.x >> 6);
    int lane = threadIdx.x & 63;
    if (d >= ndst) return;

    int beg = rowptr[d], end = rowptr[d + 1];
    float4 acc = make_float4(0.f, 0.f, 0.f, 0.f);
    const float4* f4 = (const float4*)feat;

    int i = beg;
    for (; i + 1 < end; i += 2) {
        int s0 = esrc[i], s1 = esrc[i + 1];
        float4 v0 = f4[(size_t)s0 * (DIM / 4) + lane];
        float4 v1 = f4[(size_t)s1 * (DIM / 4) + lane];
        acc.x += v0.x + v1.x; acc.y += v0.y + v1.y;
        acc.z += v0.z + v1.z; acc.w += v0.w + v1.w;
    }
    if (i < end) {
        int s0 = esrc[i];
        float4 v0 = f4[(size_t)s0 * (DIM / 4) + lane];
        acc.x += v0.x; acc.y += v0.y; acc.z += v0.z; acc.w += v0.w;
    }
    ((float4*)agg)[(size_t)d * (DIM / 4) + lane] = acc;
}

// ---------------------------------------------------------------------------
// tf32 tensor-core fused layer GEMM.
//   out[r, c] = relu( xd[r,:] @ loopw[:, c]  (K=256)
//                   + agg[r, cb*64:+64] @ W[cb][:, c%64]  (K=64)  + bias[c] )
// Block tile 128x64, 256 threads (8 warps, 4x2 warp grid, 32x32 per warp).
// K = 10 chunks of 32 (8 from xd/loopw, 2 from agg/W).
// ---------------------------------------------------------------------------
__device__ __forceinline__ uint32_t f32_to_tf32(float f) {
    uint32_t u;
    asm("cvt.rna.tf32.f32 %0, %1;" : "=r"(u) : "f"(f));
    return u;
}

template <int LAYER>
__global__ __launch_bounds__(256) void layer_kernel(
    const float* __restrict__ xparam, // layer0: x; layer1 unused
    const float* __restrict__ W,      // [4,64,64]
    const float* __restrict__ loopw,  // [256,256]
    const float* __restrict__ bias,   // [256]
    float*       __restrict__ out2,   // optional mirror (may be null)
    int M)
{
    const float* agg = (LAYER == 0) ? g_agg0 : g_agg1;
    const float* xd  = (LAYER == 0) ? xparam : g_h0;
    float*       out = (LAYER == 0) ? g_h0   : g_h1;

    __shared__ uint32_t As[128][36];   // 128 rows x 32 k (pad 36)
    __shared__ uint32_t Bs[32][72];    // 32 k x 64 n (pad 72 -> conflict-free frags)

    const int cb  = blockIdx.y;        // output column block (0..3)
    const int r0  = blockIdx.x * 128;
    const int tid = threadIdx.x;
    const int lane = tid & 31;
    const int w   = tid >> 5;          // warp 0..7
    const int wm  = w & 3;             // warp row (4)
    const int wn  = w >> 2;            // warp col (2)
    const int t4  = lane >> 2;         // 0..7
    const int tc  = lane & 3;          // 0..3

    float acc[2][4][4];
    #pragma unroll
    for (int mt = 0; mt < 2; ++mt)
        #pragma unroll
        for (int nt = 0; nt < 4; ++nt)
            #pragma unroll
            for (int i = 0; i < 4; ++i) acc[mt][nt][i] = 0.f;

    for (int ch = 0; ch < 10; ++ch) {
        const float* amat = (ch < 8) ? xd : agg;
        const int akbase  = (ch < 8) ? ch * 32 : cb * 64 + (ch - 8) * 32;

        // ---- load A tile: 128x32, 4 float4 per thread ----
        float4 av[4];
        #pragma unroll
        for (int l = 0; l < 4; ++l) {
            int idx = tid + l * 256;        // 0..1023
            int row = idx >> 3;             // /8 (8 float4 per row)
            int c4  = idx & 7;
            av[l] = make_float4(0.f, 0.f, 0.f, 0.f);
            if (r0 + row < M)
                av[l] = *(const float4*)(amat + (size_t)(r0 + row) * DIM + akbase + c4 * 4);
        }
        // ---- load B tile: 32x64, 2 float4 per thread ----
        float4 bv[2];
        #pragma unroll
        for (int l = 0; l < 2; ++l) {
            int idx = tid + l * 256;        // 0..511
            int row = idx >> 4;             // /16 (16 float4 per row)
            int c4  = idx & 15;
            if (ch < 8)
                bv[l] = *(const float4*)(loopw + (size_t)(ch * 32 + row) * DIM + cb * 64 + c4 * 4);
            else
                bv[l] = *(const float4*)(W + (size_t)cb * BD * BD
                                           + (size_t)((ch - 8) * 32 + row) * BD + c4 * 4);
        }

        __syncthreads();   // previous chunk compute done

        #pragma unroll
        for (int l = 0; l < 4; ++l) {
            int idx = tid + l * 256;
            int row = idx >> 3;
            int c4  = idx & 7;
            As[row][c4 * 4 + 0] = f32_to_tf32(av[l].x);
            As[row][c4 * 4 + 1] = f32_to_tf32(av[l].y);
            As[row][c4 * 4 + 2] = f32_to_tf32(av[l].z);
            As[row][c4 * 4 + 3] = f32_to_tf32(av[l].w);
        }
        #pragma unroll
        for (int l = 0; l < 2; ++l) {
            int idx = tid + l * 256;
            int row = idx >> 4;
            int c4  = idx & 15;
            Bs[row][c4 * 4 + 0] = f32_to_tf32(bv[l].x);
            Bs[row][c4 * 4 + 1] = f32_to_tf32(bv[l].y);
            Bs[row][c4 * 4 + 2] = f32_to_tf32(bv[l].z);
            Bs[row][c4 * 4 + 3] = f32_to_tf32(bv[l].w);
        }
        __syncthreads();

        // ---- compute: 4 k-steps of 8 ----
        #pragma unroll
        for (int k0 = 0; k0 < 32; k0 += 8) {
            uint32_t a[2][4];
            #pragma unroll
            for (int mt = 0; mt < 2; ++mt) {
                int mrow = wm * 32 + mt * 16 + t4;
                a[mt][0] = As[mrow][k0 + tc];
                a[mt][1] = As[mrow + 8][k0 + tc];
                a[mt][2] = As[mrow][k0 + tc + 4];
                a[mt][3] = As[mrow + 8][k0 + tc + 4];
            }
            #pragma unroll
            for (int nt = 0; nt < 4; ++nt) {
                int ncol = wn * 32 + nt * 8 + t4;
                uint32_t b0 = Bs[k0 + tc][ncol];
                uint32_t b1 = Bs[k0 + tc + 4][ncol];
                #pragma unroll
                for (int mt = 0; mt < 2; ++mt) {
                    asm volatile(
                        "mma.sync.aligned.m16n8k8.row.col.f32.tf32.tf32.f32 "
                        "{%0,%1,%2,%3}, {%4,%5,%6,%7}, {%8,%9}, {%0,%1,%2,%3};\n"
                        : "+f"(acc[mt][nt][0]), "+f"(acc[mt][nt][1]),
                          "+f"(acc[mt][nt][2]), "+f"(acc[mt][nt][3])
                        : "r"(a[mt][0]), "r"(a[mt][1]), "r"(a[mt][2]), "r"(a[mt][3]),
                          "r"(b0), "r"(b1));
                }
            }
        }
        __syncthreads();
    }

    // ---- epilogue: bias + relu, float2 stores ----
    #pragma unroll
    for (int nt = 0; nt < 4; ++nt) {
        int c = cb * 64 + wn * 32 + nt * 8 + 2 * tc;
        float2 bb = *(const float2*)(bias + c);
        #pragma unroll
        for (int mt = 0; mt < 2; ++mt) {
            int r = r0 + wm * 32 + mt * 16 + t4;
            if (r < M) {
                float2 o;
                o.x = fmaxf(acc[mt][nt][0] + bb.x, 0.f);
                o.y = fmaxf(acc[mt][nt][1] + bb.y, 0.f);
                *(float2*)(out + (size_t)r * DIM + c) = o;
                if (out2) *(float2*)(out2 + (size_t)r * DIM + c) = o;
            }
            if (r + 8 < M) {
                float2 o;
                o.x = fmaxf(acc[mt][nt][2] + bb.x, 0.f);
                o.y = fmaxf(acc[mt][nt][3] + bb.y, 0.f);
                *(float2*)(out + (size_t)(r + 8) * DIM + c) = o;
                if (out2) *(float2*)(out2 + (size_t)(r + 8) * DIM + c) = o;
            }
        }
    }
}

// ---------------------------------------------------------------------------
// Link predictor (unchanged): one 128-thread block per pair.
// ---------------------------------------------------------------------------
__global__ __launch_bounds__(128) void pred_kernel(
    const int*   __restrict__ ps, const int* __restrict__ pd,
    const int*   __restrict__ ns, const int* __restrict__ nd,
    const float* __restrict__ pw1,    // [256, 128]
    const float* __restrict__ pb1,    // [128]
    const float* __restrict__ pw2,    // [128]
    const float* __restrict__ pb2,    // [1]
    float*       __restrict__ out)    // [10000] : pos then neg
{
    const float* h = g_h1;
    __shared__ float e[256];
    __shared__ float ws[4];

    int p = blockIdx.x;
    const int* S;
    const int* D;
    int off;
    if (p < NPAIR) { S = ps; D = pd; off = 0; }
    else           { S = ns; D = nd; off = NPAIR; p -= NPAIR; }

    int a = S[p], b = D[p];
    int tid = threadIdx.x;   // 0..127

    e[tid]       = h[(size_t)a * DIM + tid]       * h[(size_t)b * DIM + tid];
    e[tid + 128] = h[(size_t)a * DIM + 128 + tid] * h[(size_t)b * DIM + 128 + tid];
    __syncthreads();

    float acc = pb1[tid];
    #pragma unroll 8
    for (int j = 0; j < 256; ++j)
        acc += e[j] * pw1[j * 128 + tid];
    acc = fmaxf(acc, 0.f);

    float v = acc * pw2[tid];
    #pragma unroll
    for (int o = 16; o; o >>= 1) v += __shfl_xor_sync(0xFFFFFFFFu, v, o);
    if ((tid & 31) == 0) ws[tid >> 5] = v;
    __syncthreads();
    if (tid == 0)
        out[off + p] = ws[0] + ws[1] + ws[2] + ws[3] + pb2[0];
}

// ---------------------------------------------------------------------------
// Launch
// ---------------------------------------------------------------------------
extern "C" void kernel_launch(void* const* d_in, const int* in_sizes, int n_in,
                              void* d_out, int out_size)
{
    const float* x     = (const float*)d_in[0];
    const int*   src0  = (const int*)d_in[1];
    const int*   dst0  = (const int*)d_in[2];
    const int*   src1  = (const int*)d_in[3];
    const int*   dst1  = (const int*)d_in[4];
    const int*   psrc  = (const int*)d_in[5];
    const int*   pdst  = (const int*)d_in[6];
    const int*   nsrc  = (const int*)d_in[7];
    const int*   ndst  = (const int*)d_in[8];
    const float* W0    = (const float*)d_in[9];
    const float* loop0 = (const float*)d_in[10];
    const float* b0    = (const float*)d_in[11];
    const float* W1    = (const float*)d_in[12];
    const float* loop1 = (const float*)d_in[13];
    const float* b1    = (const float*)d_in[14];
    const float* pw1   = (const float*)d_in[15];
    const float* pb1   = (const float*)d_in[16];
    const float* pw2   = (const float*)d_in[17];
    const float* pb2   = (const float*)d_in[18];
    float*       out   = (float*)d_out;

    // CSR build for both layers (edge lists are data-independent of features)
    zero_cnt_kernel<<<256, 256>>>();
    count_kernel<0><<<(NE0 + 255) / 256, 256>>>(dst0, NE0);
    count_kernel<1><<<(NE1 + 255) / 256, 256>>>(dst1, NE1);
    scan_kernel<0><<<1, 1024>>>();
    scan_kernel<1><<<1, 1024>>>();
    fill_kernel<0><<<(NE0 + 255) / 256, 256>>>(src0, dst0, NE0);
    fill_kernel<1><<<(NE1 + 255) / 256, 256>>>(src1, dst1, NE1);

    // layer 0: pull-aggregate x, fused tf32 transform -> h0
    gather_kernel<0><<<(N_DST0 + 1) / 2, 128>>>(x);
    {
        dim3 grid((N_DST0 + 127) / 128, NBASE);
        layer_kernel<0><<<grid, 256>>>(x, W0, loop0, b0, nullptr, N_DST0);
    }

    // layer 1: pull-aggregate h0, fused transform -> h1 (+mirror to out)
    gather_kernel<1><<<(N_DST1 + 1) / 2, 128>>>(nullptr);
    {
        dim3 grid((N_DST1 + 127) / 128, NBASE);
        layer_kernel<1><<<grid, 256>>>(nullptr, W1, loop1, b1,
                                       out + 2 * NPAIR, N_DST1);
    }

    // link prediction -> out[0:5000] (pos), out[5000:10000] (neg)
    pred_kernel<<<2 * NPAIR, 128>>>(psrc, pdst, nsrc, ndst,
                                    pw1, pb1, pw2, pb2, out);
}